// round 4
// baseline (speedup 1.0000x reference)
#include <cuda_runtime.h>
#include <math.h>
#include <stdint.h>

#define NB 8
#define NT 2048
#define ND 1024
#define NH 256
#define NP 512
#define NS 256

// ---------------- scratch (static device globals; no allocation) ----------------
__device__ float g_hid[NB * NT * NH];      // 16 MB
__device__ float g_scores[NB * NT];
__device__ int   g_sidx[NB * NT];
__device__ float g_sscore[NB * NT];
__device__ float g_summ[NB * NP * NS];     // 4 MB
__device__ float g_Q[NB * NT * NS];        // 16 MB
__device__ float g_K[NB * NP * NS];        // 4 MB
__device__ float g_V[NB * NP * ND];        // 16 MB
__device__ float g_logits[NB * NT * NP];   // 32 MB
__device__ int   g_cnt[NB];

// ---------------- generic tiled SGEMM: C = alpha * A(MxK) * B ----------------
template <int TRANSB>
__global__ void __launch_bounds__(256, 2)
sgemm_kernel(const float* __restrict__ A, const float* __restrict__ Bm,
             float* __restrict__ C,
             int M, int N, int K, int lda, int ldb, int ldc,
             long sA, long sB, long sC,
             const int* __restrict__ arows, long sArows,
             float alpha) {
    const int BM = 128, BN = 64, BK = 16;
    __shared__ float As[BK][BM + 4];
    __shared__ float Bs[BK][BN + 4];
    const int bz = blockIdx.z;
    const float* Ab = A + (long)bz * sA;
    const float* Bb = Bm + (long)bz * sB;
    float* Cb = C + (long)bz * sC;
    const int* rows = arows ? (arows + (long)bz * sArows) : nullptr;

    const int m0 = blockIdx.y * BM;
    const int n0 = blockIdx.x * BN;
    const int tid = threadIdx.x;          // 256 threads
    const int tx = tid & 15;              // 16 col-groups * 4
    const int ty = tid >> 4;              // 16 row-groups * 8

    float acc[8][4];
#pragma unroll
    for (int i = 0; i < 8; i++)
#pragma unroll
        for (int j = 0; j < 4; j++) acc[i][j] = 0.f;

    for (int k0 = 0; k0 < K; k0 += BK) {
#pragma unroll
        for (int i = 0; i < 8; i++) {
            int e = tid + i * 256;
            int r = e >> 4, kk = e & 15;
            long arow = rows ? (long)rows[m0 + r] : (long)(m0 + r);
            As[kk][r] = Ab[arow * (long)lda + k0 + kk];
        }
#pragma unroll
        for (int i = 0; i < 4; i++) {
            int e = tid + i * 256;
            if (TRANSB == 0) {
                int kk = e >> 6, c = e & 63;
                Bs[kk][c] = Bb[(long)(k0 + kk) * ldb + n0 + c];
            } else {
                int c = e >> 4, kk = e & 15;
                Bs[kk][c] = Bb[(long)(n0 + c) * ldb + k0 + kk];
            }
        }
        __syncthreads();
#pragma unroll
        for (int kk = 0; kk < BK; kk++) {
            float a[8], b[4];
#pragma unroll
            for (int i = 0; i < 8; i++) a[i] = As[kk][ty * 8 + i];
#pragma unroll
            for (int j = 0; j < 4; j++) b[j] = Bs[kk][tx * 4 + j];
#pragma unroll
            for (int i = 0; i < 8; i++)
#pragma unroll
                for (int j = 0; j < 4; j++) acc[i][j] = __fmaf_rn(a[i], b[j], acc[i][j]);
        }
        __syncthreads();
    }
#pragma unroll
    for (int i = 0; i < 8; i++) {
        long r = m0 + ty * 8 + i;
#pragma unroll
        for (int j = 0; j < 4; j++)
            Cb[r * (long)ldc + n0 + tx * 4 + j] = alpha * acc[i][j];
    }
}

// ---------------- hid GEMM with Eigen gebp K-panel structure ----------------
// Eigen (XLA-CPU, aarch64 defaults: L1=16KB, mr=12, nr=4) splits K=1024 into
// kc=248 panels: [248,248,248,248,32]. Each panel is an independent sequential
// FMA chain from 0; panels combine into C with plain fadd.
__global__ void __launch_bounds__(256, 2)
hid_gemm_kernel(const float* __restrict__ A, const float* __restrict__ Bm,
                float* __restrict__ C) {
    const int BM = 128, BN = 64, BK = 8;
    __shared__ float As[BK][BM + 4];
    __shared__ float Bs[BK][BN + 4];
    const int m0 = blockIdx.y * BM;
    const int n0 = blockIdx.x * BN;
    const int tid = threadIdx.x;          // 256 threads
    const int tx = tid & 15;
    const int ty = tid >> 4;

    float tot[8][4], pan[8][4];
#pragma unroll
    for (int i = 0; i < 8; i++)
#pragma unroll
        for (int j = 0; j < 4; j++) { tot[i][j] = 0.f; pan[i][j] = 0.f; }

    for (int k0 = 0; k0 < 1024; k0 += BK) {
        // A tile: 128x8 = 1024 elems, 4 per thread
#pragma unroll
        for (int i = 0; i < 4; i++) {
            int e = tid + i * 256;
            int r = e >> 3, kk = e & 7;
            As[kk][r] = A[(long)(m0 + r) * 1024 + k0 + kk];
        }
        // B tile: 8x64 = 512 elems, 2 per thread
#pragma unroll
        for (int i = 0; i < 2; i++) {
            int e = tid + i * 256;
            int kk = e >> 6, c = e & 63;
            Bs[kk][c] = Bm[(long)(k0 + kk) * 256 + n0 + c];
        }
        __syncthreads();
#pragma unroll
        for (int kk = 0; kk < BK; kk++) {
            float a[8], b[4];
#pragma unroll
            for (int i = 0; i < 8; i++) a[i] = As[kk][ty * 8 + i];
#pragma unroll
            for (int j = 0; j < 4; j++) b[j] = Bs[kk][tx * 4 + j];
#pragma unroll
            for (int i = 0; i < 8; i++)
#pragma unroll
                for (int j = 0; j < 4; j++) pan[i][j] = __fmaf_rn(a[i], b[j], pan[i][j]);
        }
        __syncthreads();
        int kend = k0 + BK;
        if (kend == 248 || kend == 496 || kend == 744 || kend == 992 || kend == 1024) {
#pragma unroll
            for (int i = 0; i < 8; i++)
#pragma unroll
                for (int j = 0; j < 4; j++) {
                    tot[i][j] = __fadd_rn(tot[i][j], pan[i][j]);
                    pan[i][j] = 0.f;
                }
        }
    }
#pragma unroll
    for (int i = 0; i < 8; i++) {
        long r = m0 + ty * 8 + i;
#pragma unroll
        for (int j = 0; j < 4; j++)
            C[r * 256 + n0 + tx * 4 + j] = tot[i][j];
    }
}

// ---------------- XLA-CPU f32 tanh (Cephes-style rational P/Q, no contraction) ----------------
__device__ __forceinline__ float xla_tanh_f32(float x) {
    const float kClamp = 7.90531110763549805f;
    float xc = fminf(fmaxf(x, -kClamp), kClamp);
    float x2 = __fmul_rn(xc, xc);
    float p = -2.76076847742355e-16f;
    p = __fadd_rn(__fmul_rn(p, x2), 2.00018790482477e-13f);
    p = __fadd_rn(__fmul_rn(p, x2), -8.60467152213735e-11f);
    p = __fadd_rn(__fmul_rn(p, x2), 5.12229709037114e-08f);
    p = __fadd_rn(__fmul_rn(p, x2), 1.48572235717979e-05f);
    p = __fadd_rn(__fmul_rn(p, x2), 6.37261928875436e-04f);
    p = __fadd_rn(__fmul_rn(p, x2), 4.89352455891786e-03f);
    p = __fmul_rn(xc, p);
    float q = 1.19825839466702e-06f;
    q = __fadd_rn(__fmul_rn(q, x2), 1.18534705686654e-04f);
    q = __fadd_rn(__fmul_rn(q, x2), 2.26843463243900e-03f);
    q = __fadd_rn(__fmul_rn(q, x2), 4.89352518554385e-03f);
    float r = __fdiv_rn(p, q);
    return (fabsf(x) < 0.0004f) ? x : r;
}

// XLA logistic expander: 0.5 + 0.5 * tanh(0.5 * x), non-contracted
__device__ __forceinline__ float xla_sigmoid_f32(float x) {
    return __fadd_rn(0.5f, __fmul_rn(0.5f, xla_tanh_f32(__fmul_rn(0.5f, x))));
}

// ---------------- scores: XLA-CPU tiled LLVM-IR gemv replica ----------------
// 4 striped accumulators (lane = k mod 4), UNFUSED mul+add per element,
// pairwise combine (a0+a2)+(a1+a3).
__global__ void score_gemv_kernel(const float* __restrict__ hid,
                                  const float* __restrict__ w2,
                                  float* __restrict__ scores, int nrows) {
    int r = blockIdx.x * blockDim.x + threadIdx.x;
    if (r >= nrows) return;
    const float* h = hid + (long)r * NH;
    float a0 = 0.f, a1 = 0.f, a2 = 0.f, a3 = 0.f;
#pragma unroll 4
    for (int k = 0; k < NH; k += 4) {
        float v0 = fmaxf(h[k + 0], 0.f);
        float v1 = fmaxf(h[k + 1], 0.f);
        float v2 = fmaxf(h[k + 2], 0.f);
        float v3 = fmaxf(h[k + 3], 0.f);
        a0 = __fadd_rn(__fmul_rn(v0, __ldg(&w2[k + 0])), a0);
        a1 = __fadd_rn(__fmul_rn(v1, __ldg(&w2[k + 1])), a1);
        a2 = __fadd_rn(__fmul_rn(v2, __ldg(&w2[k + 2])), a2);
        a3 = __fadd_rn(__fmul_rn(v3, __ldg(&w2[k + 3])), a3);
    }
    float s = __fadd_rn(__fadd_rn(a0, a2), __fadd_rn(a1, a3));
    scores[r] = xla_sigmoid_f32(s);
}

// ---------------- per-batch descending stable sort (bitonic over 2048) ----------------
__global__ void sort_kernel(const float* __restrict__ scores,
                            int* __restrict__ sidx, float* __restrict__ sscore) {
    __shared__ unsigned long long key[NT];
    const int b = blockIdx.x;
    const int tid = threadIdx.x;  // 1024
    for (int i = tid; i < NT; i += 1024) {
        unsigned int bits = __float_as_uint(scores[b * NT + i]);  // scores > 0 => monotonic
        key[i] = ((unsigned long long)(0xFFFFFFFFu - bits) << 32) | (unsigned int)i;
    }
    __syncthreads();
    for (int k = 2; k <= NT; k <<= 1) {
        for (int j = k >> 1; j > 0; j >>= 1) {
            for (int i = tid; i < NT; i += 1024) {
                int p = i ^ j;
                if (p > i) {
                    bool up = ((i & k) == 0);
                    unsigned long long a = key[i], c = key[p];
                    if ((a > c) == up) { key[i] = c; key[p] = a; }
                }
            }
            __syncthreads();
        }
    }
    for (int i = tid; i < NT; i += 1024) {
        unsigned long long k = key[i];
        sidx[b * NT + i] = (int)(k & 0xFFFFFFFFull);
        sscore[b * NT + i] = __uint_as_float(0xFFFFFFFFu - (unsigned int)(k >> 32));
    }
}

// ---------------- sequential pool update (exact reference semantics) ----------------
__global__ void update_kernel(const float* __restrict__ pool_in,
                              const float* __restrict__ pri_in,
                              const int* __restrict__ counts_in,
                              const float* __restrict__ sscore,
                              const float* __restrict__ summ,
                              float* __restrict__ pool_out,
                              float* __restrict__ pri_out,
                              float* __restrict__ cnt_out_f,
                              int* __restrict__ cnt_out) {
    const int b = blockIdx.x;
    const int tid = threadIdx.x;  // 256
    const float4* src = (const float4*)(pool_in + (long)b * NP * NS);
    float4* dst = (float4*)(pool_out + (long)b * NP * NS);
    for (int i = tid; i < NP * NS / 4; i += 256) dst[i] = src[i];
    __syncthreads();
    if (tid >= 32) return;
    const int lane = tid;

    float pr[16];
#pragma unroll
    for (int j = 0; j < 16; j++) pr[j] = pri_in[b * NP + j * 32 + lane];
    int count = counts_in[b];
    const float* ss = sscore + (long)b * NT;

    for (int s = 0; s < NP; s++) {
        float imp = ss[s];
        if (!(imp > 0.5f)) break;  // sorted descending; rest also fail mask
        const float4* srow = (const float4*)(summ + ((long)b * NP + s) * NS);
        if (count < NP) {
            int idx = count;
            float4* drow = (float4*)(pool_out + ((long)b * NP + idx) * NS);
            drow[lane] = srow[lane];
            drow[lane + 32] = srow[lane + 32];
            if ((idx & 31) == lane) pr[idx >> 5] = imp;
            count++;
        }
        if (count >= NP) {
            float bv = pr[0];
            int bi = lane;
#pragma unroll
            for (int j = 1; j < 16; j++) {
                float v = pr[j];
                if (v < bv) { bv = v; bi = j * 32 + lane; }
            }
#pragma unroll
            for (int o = 16; o > 0; o >>= 1) {
                float ov = __shfl_xor_sync(0xFFFFFFFFu, bv, o);
                int oi = __shfl_xor_sync(0xFFFFFFFFu, bi, o);
                if (ov < bv || (ov == bv && oi < bi)) { bv = ov; bi = oi; }
            }
            if (imp > bv) {
                float4* drow = (float4*)(pool_out + ((long)b * NP + bi) * NS);
                drow[lane] = srow[lane];
                drow[lane + 32] = srow[lane + 32];
                if ((bi & 31) == lane) pr[bi >> 5] = imp;
            }
        }
    }
#pragma unroll
    for (int j = 0; j < 16; j++) pri_out[b * NP + j * 32 + lane] = pr[j];
    if (lane == 0) { cnt_out_f[b] = (float)count; cnt_out[b] = count; }
}

// ---------------- masked softmax over P=512 (one warp per row, in place) ----------------
__global__ void softmax_kernel(float* __restrict__ logits, const int* __restrict__ cnt) {
    int row = (blockIdx.x * blockDim.x + threadIdx.x) >> 5;
    if (row >= NB * NT) return;
    const int lane = threadIdx.x & 31;
    const int b = row / NT;
    const int c = cnt[b];
    float* L = logits + (long)row * NP;
    float v[16];
    float mx = -INFINITY;
#pragma unroll
    for (int j = 0; j < 16; j++) {
        int p = j * 32 + lane;
        float x = (p < c) ? L[p] : -INFINITY;
        v[j] = x;
        mx = fmaxf(mx, x);
    }
#pragma unroll
    for (int o = 16; o > 0; o >>= 1) mx = fmaxf(mx, __shfl_xor_sync(0xFFFFFFFFu, mx, o));
    if (mx == -INFINITY) {
#pragma unroll
        for (int j = 0; j < 16; j++) v[j] = 0.f;  // nan_to_num(softmax(all -inf)) == 0
    } else {
        float sum = 0.f;
#pragma unroll
        for (int j = 0; j < 16; j++) {
            v[j] = (v[j] == -INFINITY) ? 0.f : expf(v[j] - mx);
            sum += v[j];
        }
#pragma unroll
        for (int o = 16; o > 0; o >>= 1) sum += __shfl_xor_sync(0xFFFFFFFFu, sum, o);
        float inv = 1.f / sum;
#pragma unroll
        for (int j = 0; j < 16; j++) v[j] *= inv;
    }
#pragma unroll
    for (int j = 0; j < 16; j++) L[j * 32 + lane] = v[j];
}

// ---------------- launch ----------------
extern "C" void kernel_launch(void* const* d_in, const int* in_sizes, int n_in,
                              void* d_out, int out_size) {
    const float* tokens = (const float*)d_in[0];
    const float* pool   = (const float*)d_in[1];
    const float* pri    = (const float*)d_in[2];
    const int*   counts = (const int*)d_in[3];
    const float* w1     = (const float*)d_in[4];
    const float* w2     = (const float*)d_in[5];
    const float* w_sum  = (const float*)d_in[6];
    const float* wq     = (const float*)d_in[7];
    const float* wk     = (const float*)d_in[8];
    const float* wv     = (const float*)d_in[9];

    float* out = (float*)d_out;
    float* out_ret  = out;                                   // [8,2048,1024]
    float* out_pool = out + (long)NB * NT * ND;              // [8,512,256]
    float* out_pri  = out_pool + (long)NB * NP * NS;         // [8,512]
    float* out_cnt  = out_pri + (long)NB * NP;               // [8]

    float *p_hid, *p_scores, *p_sscore, *p_summ, *p_Q, *p_K, *p_V, *p_logits;
    int *p_sidx, *p_cnt;
    cudaGetSymbolAddress((void**)&p_hid, g_hid);
    cudaGetSymbolAddress((void**)&p_scores, g_scores);
    cudaGetSymbolAddress((void**)&p_sidx, g_sidx);
    cudaGetSymbolAddress((void**)&p_sscore, g_sscore);
    cudaGetSymbolAddress((void**)&p_summ, g_summ);
    cudaGetSymbolAddress((void**)&p_Q, g_Q);
    cudaGetSymbolAddress((void**)&p_K, g_K);
    cudaGetSymbolAddress((void**)&p_V, g_V);
    cudaGetSymbolAddress((void**)&p_logits, g_logits);
    cudaGetSymbolAddress((void**)&p_cnt, g_cnt);

    // 1) hid = tokens @ w1 with Eigen K-panel accumulation structure
    hid_gemm_kernel<<<dim3(256 / 64, 16384 / 128, 1), 256>>>(tokens, w1, p_hid);
    // 2) scores = xla_sigmoid(relu(hid) . w2), XLA gemv replica
    score_gemv_kernel<<<16384 / 256, 256>>>(p_hid, w2, p_scores, 16384);
    // 3) per-batch descending stable sort
    sort_kernel<<<NB, 1024>>>(p_scores, p_sidx, p_sscore);
    // 4) summaries = sorted_tokens[:,:512] @ w_sum (batched, gathered A)
    sgemm_kernel<0><<<dim3(256 / 64, 512 / 128, NB), 256>>>(
        tokens, w_sum, p_summ, 512, 256, 1024, 1024, 256, 256,
        (long)NT * ND, 0, (long)NP * NS, p_sidx, NT, 1.f);
    // 5) Q = tokens @ wq (independent of update)
    sgemm_kernel<0><<<dim3(256 / 64, 16384 / 128, 1), 256>>>(
        tokens, wq, p_Q, 16384, 256, 1024, 1024, 256, 256, 0, 0, 0, nullptr, 0, 1.f);
    // 6) sequential pool update
    update_kernel<<<NB, 256>>>(pool, pri, counts, p_sscore, p_summ,
                               out_pool, out_pri, out_cnt, p_cnt);
    // 7) K = pool_out @ wk (M=4096, N=256, K=256)
    sgemm_kernel<0><<<dim3(256 / 64, 4096 / 128, 1), 256>>>(
        out_pool, wk, p_K, 4096, 256, 256, 256, 256, 256, 0, 0, 0, nullptr, 0, 1.f);
    // 8) V = pool_out @ wv (M=4096, N=1024, K=256)
    sgemm_kernel<0><<<dim3(1024 / 64, 4096 / 128, 1), 256>>>(
        out_pool, wv, p_V, 4096, 1024, 256, 256, 1024, 1024, 0, 0, 0, nullptr, 0, 1.f);
    // 9) logits = Q @ K^T / 16 (batched NT form)
    sgemm_kernel<1><<<dim3(512 / 64, 2048 / 128, NB), 256>>>(
        p_Q, p_K, p_logits, 2048, 512, 256, 256, 256, 512,
        (long)NT * NS, (long)NP * NS, (long)NT * NP, nullptr, 0, 1.f / 16.f);
    // 10) masked softmax in place
    softmax_kernel<<<(16384 * 32) / 256, 256>>>(p_logits, p_cnt);
    // 11) retrieved = attn @ V (batched)
    sgemm_kernel<0><<<dim3(1024 / 64, 2048 / 128, NB), 256>>>(
        p_logits, p_V, out_ret, 2048, 1024, 512, 512, 1024, 1024,
        (long)NT * NP, (long)NP * ND, (long)NT * ND, nullptr, 0, 1.f);
}

// round 6
// speedup vs baseline: 1.0404x; 1.0404x over previous
#include <cuda_runtime.h>
#include <math.h>
#include <stdint.h>

#define NB 8
#define NT 2048
#define ND 1024
#define NH 256
#define NP 512
#define NS 256

typedef unsigned long long u64;

// ---------------- packed f32x2 helpers (Blackwell FFMA2 via PTX) ----------------
__device__ __forceinline__ u64 pack2same(float x) {
    u64 r;
    asm("mov.b64 %0, {%1, %1};" : "=l"(r) : "r"(__float_as_uint(x)));
    return r;
}
__device__ __forceinline__ void ffma2(u64& d, u64 a, u64 b) {
    asm("fma.rn.f32x2 %0, %1, %2, %0;" : "+l"(d) : "l"(a), "l"(b));
}
__device__ __forceinline__ void fadd2(u64& d, u64 a) {
    asm("add.rn.f32x2 %0, %0, %1;" : "+l"(d) : "l"(a));
}
__device__ __forceinline__ void unpack2(u64 v, float& lo, float& hi) {
    unsigned a, b;
    asm("mov.b64 {%0, %1}, %2;" : "=r"(a), "=r"(b) : "l"(v));
    lo = __uint_as_float(a); hi = __uint_as_float(b);
}

// ---------------- scratch (static device globals; no allocation) ----------------
__device__ float g_hid[NB * NT * NH];      // 16 MB
__device__ float g_scores[NB * NT];
__device__ int   g_sidx[NB * NT];
__device__ float g_sscore[NB * NT];
__device__ float g_summ[NB * NP * NS];     // 4 MB
__device__ float g_Q[NB * NT * NS];        // 16 MB
__device__ float g_K[NB * NP * NS];        // 4 MB
__device__ float g_V[NB * NP * ND];        // 16 MB
__device__ float g_logits[NB * NT * NP];   // 32 MB
__device__ int   g_cnt[NB];

// ---------------- fast 128x128x16 SGEMM with packed FFMA2 ----------------
// C = alpha * A(MxK) * B. TRANSB==0: B[K,N] row-major. TRANSB==1: B[N,K] (C=A*B^T).
// Optional row-gather on A. Batched via blockIdx.z. M,N multiples of 128, K of 16.
template <int TRANSB>
__global__ void __launch_bounds__(256, 2)
sgemm128_kernel(const float* __restrict__ A, const float* __restrict__ Bm,
                float* __restrict__ C,
                int K, int lda, int ldb, int ldc,
                long sA, long sB, long sC,
                const int* __restrict__ arows, long sArows,
                float alpha) {
    __shared__ float As[128][20];   // [row][k], stride 20 (f4-aligned stores)
    __shared__ float Bs[16][132];   // [k][n]
    const int bz = blockIdx.z;
    const float* Ab = A + (long)bz * sA;
    const float* Bb = Bm + (long)bz * sB;
    float* Cb = C + (long)bz * sC;
    const int* rows = arows ? (arows + (long)bz * sArows) : nullptr;

    const int m0 = blockIdx.y * 128;
    const int n0 = blockIdx.x * 128;
    const int tid = threadIdx.x;   // 256
    const int tx = tid & 15;       // 16 col groups * 8
    const int ty = tid >> 4;       // 16 row groups * 8

    u64 acc2[8][4];
#pragma unroll
    for (int i = 0; i < 8; i++)
#pragma unroll
        for (int j = 0; j < 4; j++) acc2[i][j] = 0ull;

    for (int k0 = 0; k0 < K; k0 += 16) {
        // A tile: 128x16 = 512 float4, 2 per thread
#pragma unroll
        for (int i = 0; i < 2; i++) {
            int e = tid + i * 256;
            int r = e >> 2, kq = e & 3;
            long arow = rows ? (long)rows[m0 + r] : (long)(m0 + r);
            float4 v = *(const float4*)(Ab + arow * (long)lda + k0 + kq * 4);
            *(float4*)&As[r][kq * 4] = v;
        }
        // B tile: 16x128 = 512 float4, 2 per thread
#pragma unroll
        for (int i = 0; i < 2; i++) {
            int e = tid + i * 256;
            if (TRANSB == 0) {
                int k = e >> 5, nq = e & 31;
                float4 v = *(const float4*)(Bb + (long)(k0 + k) * ldb + n0 + nq * 4);
                *(float4*)&Bs[k][nq * 4] = v;
            } else {
                int n = e >> 2, kq = e & 3;
                float4 v = *(const float4*)(Bb + (long)(n0 + n) * ldb + k0 + kq * 4);
                Bs[kq * 4 + 0][n] = v.x;
                Bs[kq * 4 + 1][n] = v.y;
                Bs[kq * 4 + 2][n] = v.z;
                Bs[kq * 4 + 3][n] = v.w;
            }
        }
        __syncthreads();
#pragma unroll
        for (int kk = 0; kk < 16; kk++) {
            u64 a2[8], b2[4];
#pragma unroll
            for (int i = 0; i < 8; i++) a2[i] = pack2same(As[ty * 8 + i][kk]);
#pragma unroll
            for (int j = 0; j < 4; j++)
                b2[j] = *(const u64*)&Bs[kk][tx * 8 + 2 * j];
#pragma unroll
            for (int i = 0; i < 8; i++)
#pragma unroll
                for (int j = 0; j < 4; j++) ffma2(acc2[i][j], a2[i], b2[j]);
        }
        __syncthreads();
    }
#pragma unroll
    for (int i = 0; i < 8; i++) {
        long r = m0 + ty * 8 + i;
        float o[8];
#pragma unroll
        for (int j = 0; j < 4; j++) unpack2(acc2[i][j], o[2 * j], o[2 * j + 1]);
#pragma unroll
        for (int j = 0; j < 8; j++) o[j] *= alpha;
        float* cp = Cb + r * (long)ldc + n0 + tx * 8;
        *(float4*)cp = make_float4(o[0], o[1], o[2], o[3]);
        *(float4*)(cp + 4) = make_float4(o[4], o[5], o[6], o[7]);
    }
}

// ---------------- hid GEMM with Eigen gebp K-panel structure (FFMA2 inner) ----------------
// kc=248 panels [248,248,248,248,32]; per-panel FMA chains combined with fadd.
// f32x2 lanes are IEEE fp32 ops -> bitwise identical to the scalar version.
__global__ void __launch_bounds__(256, 2)
hid_gemm_kernel(const float* __restrict__ A, const float* __restrict__ Bm,
                float* __restrict__ C) {
    const int BM = 128, BN = 64, BK = 8;
    __shared__ float As[BK][BM + 4];
    __shared__ float Bs[BK][BN + 4];
    const int m0 = blockIdx.y * BM;
    const int n0 = blockIdx.x * BN;
    const int tid = threadIdx.x;
    const int tx = tid & 15;
    const int ty = tid >> 4;

    u64 tot2[8][2], pan2[8][2];
#pragma unroll
    for (int i = 0; i < 8; i++)
#pragma unroll
        for (int j = 0; j < 2; j++) { tot2[i][j] = 0ull; pan2[i][j] = 0ull; }

    for (int k0 = 0; k0 < 1024; k0 += BK) {
#pragma unroll
        for (int i = 0; i < 4; i++) {
            int e = tid + i * 256;
            int r = e >> 3, kk = e & 7;
            As[kk][r] = A[(long)(m0 + r) * 1024 + k0 + kk];
        }
#pragma unroll
        for (int i = 0; i < 2; i++) {
            int e = tid + i * 256;
            int kk = e >> 6, c = e & 63;
            Bs[kk][c] = Bm[(long)(k0 + kk) * 256 + n0 + c];
        }
        __syncthreads();
#pragma unroll
        for (int kk = 0; kk < BK; kk++) {
            u64 a2[8], b2[2];
#pragma unroll
            for (int i = 0; i < 8; i++) a2[i] = pack2same(As[kk][ty * 8 + i]);
#pragma unroll
            for (int j = 0; j < 2; j++)
                b2[j] = *(const u64*)&Bs[kk][tx * 4 + 2 * j];
#pragma unroll
            for (int i = 0; i < 8; i++)
#pragma unroll
                for (int j = 0; j < 2; j++) ffma2(pan2[i][j], a2[i], b2[j]);
        }
        __syncthreads();
        int kend = k0 + BK;
        if (kend == 248 || kend == 496 || kend == 744 || kend == 992 || kend == 1024) {
#pragma unroll
            for (int i = 0; i < 8; i++)
#pragma unroll
                for (int j = 0; j < 2; j++) {
                    fadd2(tot2[i][j], pan2[i][j]);
                    pan2[i][j] = 0ull;
                }
        }
    }
#pragma unroll
    for (int i = 0; i < 8; i++) {
        long r = m0 + ty * 8 + i;
        float o[4];
#pragma unroll
        for (int j = 0; j < 2; j++) unpack2(tot2[i][j], o[2 * j], o[2 * j + 1]);
        float* cp = C + r * 256 + n0 + tx * 4;
        *(float4*)cp = make_float4(o[0], o[1], o[2], o[3]);
    }
}

// ---------------- XLA-CPU f32 tanh (Cephes-style rational P/Q, no contraction) ----------------
__device__ __forceinline__ float xla_tanh_f32(float x) {
    const float kClamp = 7.90531110763549805f;
    float xc = fminf(fmaxf(x, -kClamp), kClamp);
    float x2 = __fmul_rn(xc, xc);
    float p = -2.76076847742355e-16f;
    p = __fadd_rn(__fmul_rn(p, x2), 2.00018790482477e-13f);
    p = __fadd_rn(__fmul_rn(p, x2), -8.60467152213735e-11f);
    p = __fadd_rn(__fmul_rn(p, x2), 5.12229709037114e-08f);
    p = __fadd_rn(__fmul_rn(p, x2), 1.48572235717979e-05f);
    p = __fadd_rn(__fmul_rn(p, x2), 6.37261928875436e-04f);
    p = __fadd_rn(__fmul_rn(p, x2), 4.89352455891786e-03f);
    p = __fmul_rn(xc, p);
    float q = 1.19825839466702e-06f;
    q = __fadd_rn(__fmul_rn(q, x2), 1.18534705686654e-04f);
    q = __fadd_rn(__fmul_rn(q, x2), 2.26843463243900e-03f);
    q = __fadd_rn(__fmul_rn(q, x2), 4.89352518554385e-03f);
    float r = __fdiv_rn(p, q);
    return (fabsf(x) < 0.0004f) ? x : r;
}

__device__ __forceinline__ float xla_sigmoid_f32(float x) {
    return __fadd_rn(0.5f, __fmul_rn(0.5f, xla_tanh_f32(__fmul_rn(0.5f, x))));
}

// ---------------- scores: XLA-CPU tiled LLVM-IR gemv replica ----------------
__global__ void score_gemv_kernel(const float* __restrict__ hid,
                                  const float* __restrict__ w2,
                                  float* __restrict__ scores, int nrows) {
    int r = blockIdx.x * blockDim.x + threadIdx.x;
    if (r >= nrows) return;
    const float* h = hid + (long)r * NH;
    float a0 = 0.f, a1 = 0.f, a2 = 0.f, a3 = 0.f;
#pragma unroll 4
    for (int k = 0; k < NH; k += 4) {
        float v0 = fmaxf(h[k + 0], 0.f);
        float v1 = fmaxf(h[k + 1], 0.f);
        float v2 = fmaxf(h[k + 2], 0.f);
        float v3 = fmaxf(h[k + 3], 0.f);
        a0 = __fadd_rn(__fmul_rn(v0, __ldg(&w2[k + 0])), a0);
        a1 = __fadd_rn(__fmul_rn(v1, __ldg(&w2[k + 1])), a1);
        a2 = __fadd_rn(__fmul_rn(v2, __ldg(&w2[k + 2])), a2);
        a3 = __fadd_rn(__fmul_rn(v3, __ldg(&w2[k + 3])), a3);
    }
    float s = __fadd_rn(__fadd_rn(a0, a2), __fadd_rn(a1, a3));
    scores[r] = xla_sigmoid_f32(s);
}

// ---------------- per-batch descending stable sort (bitonic over 2048) ----------------
__global__ void sort_kernel(const float* __restrict__ scores,
                            int* __restrict__ sidx, float* __restrict__ sscore) {
    __shared__ unsigned long long key[NT];
    const int b = blockIdx.x;
    const int tid = threadIdx.x;  // 1024
    for (int i = tid; i < NT; i += 1024) {
        unsigned int bits = __float_as_uint(scores[b * NT + i]);
        key[i] = ((unsigned long long)(0xFFFFFFFFu - bits) << 32) | (unsigned int)i;
    }
    __syncthreads();
    for (int k = 2; k <= NT; k <<= 1) {
        for (int j = k >> 1; j > 0; j >>= 1) {
            for (int i = tid; i < NT; i += 1024) {
                int p = i ^ j;
                if (p > i) {
                    bool up = ((i & k) == 0);
                    unsigned long long a = key[i], c = key[p];
                    if ((a > c) == up) { key[i] = c; key[p] = a; }
                }
            }
            __syncthreads();
        }
    }
    for (int i = tid; i < NT; i += 1024) {
        unsigned long long k = key[i];
        sidx[b * NT + i] = (int)(k & 0xFFFFFFFFull);
        sscore[b * NT + i] = __uint_as_float(0xFFFFFFFFu - (unsigned int)(k >> 32));
    }
}

// ---------------- sequential pool update (exact reference semantics) ----------------
__global__ void update_kernel(const float* __restrict__ pool_in,
                              const float* __restrict__ pri_in,
                              const int* __restrict__ counts_in,
                              const float* __restrict__ sscore,
                              const float* __restrict__ summ,
                              float* __restrict__ pool_out,
                              float* __restrict__ pri_out,
                              float* __restrict__ cnt_out_f,
                              int* __restrict__ cnt_out) {
    const int b = blockIdx.x;
    const int tid = threadIdx.x;  // 256
    const float4* src = (const float4*)(pool_in + (long)b * NP * NS);
    float4* dst = (float4*)(pool_out + (long)b * NP * NS);
    for (int i = tid; i < NP * NS / 4; i += 256) dst[i] = src[i];
    __syncthreads();
    if (tid >= 32) return;
    const int lane = tid;

    float pr[16];
#pragma unroll
    for (int j = 0; j < 16; j++) pr[j] = pri_in[b * NP + j * 32 + lane];
    int count = counts_in[b];
    const float* ss = sscore + (long)b * NT;

    for (int s = 0; s < NP; s++) {
        float imp = ss[s];
        if (!(imp > 0.5f)) break;
        const float4* srow = (const float4*)(summ + ((long)b * NP + s) * NS);
        if (count < NP) {
            int idx = count;
            float4* drow = (float4*)(pool_out + ((long)b * NP + idx) * NS);
            drow[lane] = srow[lane];
            drow[lane + 32] = srow[lane + 32];
            if ((idx & 31) == lane) pr[idx >> 5] = imp;
            count++;
        }
        if (count >= NP) {
            float bv = pr[0];
            int bi = lane;
#pragma unroll
            for (int j = 1; j < 16; j++) {
                float v = pr[j];
                if (v < bv) { bv = v; bi = j * 32 + lane; }
            }
#pragma unroll
            for (int o = 16; o > 0; o >>= 1) {
                float ov = __shfl_xor_sync(0xFFFFFFFFu, bv, o);
                int oi = __shfl_xor_sync(0xFFFFFFFFu, bi, o);
                if (ov < bv || (ov == bv && oi < bi)) { bv = ov; bi = oi; }
            }
            if (imp > bv) {
                float4* drow = (float4*)(pool_out + ((long)b * NP + bi) * NS);
                drow[lane] = srow[lane];
                drow[lane + 32] = srow[lane + 32];
                if ((bi & 31) == lane) pr[bi >> 5] = imp;
            }
        }
    }
#pragma unroll
    for (int j = 0; j < 16; j++) pri_out[b * NP + j * 32 + lane] = pr[j];
    if (lane == 0) { cnt_out_f[b] = (float)count; cnt_out[b] = count; }
}

// ---------------- masked softmax over P=512 (one warp per row, in place) ----------------
__global__ void softmax_kernel(float* __restrict__ logits, const int* __restrict__ cnt) {
    int row = (blockIdx.x * blockDim.x + threadIdx.x) >> 5;
    if (row >= NB * NT) return;
    const int lane = threadIdx.x & 31;
    const int b = row / NT;
    const int c = cnt[b];
    float* L = logits + (long)row * NP;
    float v[16];
    float mx = -INFINITY;
#pragma unroll
    for (int j = 0; j < 16; j++) {
        int p = j * 32 + lane;
        float x = (p < c) ? L[p] : -INFINITY;
        v[j] = x;
        mx = fmaxf(mx, x);
    }
#pragma unroll
    for (int o = 16; o > 0; o >>= 1) mx = fmaxf(mx, __shfl_xor_sync(0xFFFFFFFFu, mx, o));
    if (mx == -INFINITY) {
#pragma unroll
        for (int j = 0; j < 16; j++) v[j] = 0.f;
    } else {
        float sum = 0.f;
#pragma unroll
        for (int j = 0; j < 16; j++) {
            v[j] = (v[j] == -INFINITY) ? 0.f : expf(v[j] - mx);
            sum += v[j];
        }
#pragma unroll
        for (int o = 16; o > 0; o >>= 1) sum += __shfl_xor_sync(0xFFFFFFFFu, sum, o);
        float inv = 1.f / sum;
#pragma unroll
        for (int j = 0; j < 16; j++) v[j] *= inv;
    }
#pragma unroll
    for (int j = 0; j < 16; j++) L[j * 32 + lane] = v[j];
}

// ---------------- launch ----------------
extern "C" void kernel_launch(void* const* d_in, const int* in_sizes, int n_in,
                              void* d_out, int out_size) {
    const float* tokens = (const float*)d_in[0];
    const float* pool   = (const float*)d_in[1];
    const float* pri    = (const float*)d_in[2];
    const int*   counts = (const int*)d_in[3];
    const float* w1     = (const float*)d_in[4];
    const float* w2     = (const float*)d_in[5];
    const float* w_sum  = (const float*)d_in[6];
    const float* wq     = (const float*)d_in[7];
    const float* wk     = (const float*)d_in[8];
    const float* wv     = (const float*)d_in[9];

    float* out = (float*)d_out;
    float* out_ret  = out;                                   // [8,2048,1024]
    float* out_pool = out + (long)NB * NT * ND;              // [8,512,256]
    float* out_pri  = out_pool + (long)NB * NP * NS;         // [8,512]
    float* out_cnt  = out_pri + (long)NB * NP;               // [8]

    float *p_hid, *p_scores, *p_sscore, *p_summ, *p_Q, *p_K, *p_V, *p_logits;
    int *p_sidx, *p_cnt;
    cudaGetSymbolAddress((void**)&p_hid, g_hid);
    cudaGetSymbolAddress((void**)&p_scores, g_scores);
    cudaGetSymbolAddress((void**)&p_sidx, g_sidx);
    cudaGetSymbolAddress((void**)&p_sscore, g_sscore);
    cudaGetSymbolAddress((void**)&p_summ, g_summ);
    cudaGetSymbolAddress((void**)&p_Q, g_Q);
    cudaGetSymbolAddress((void**)&p_K, g_K);
    cudaGetSymbolAddress((void**)&p_V, g_V);
    cudaGetSymbolAddress((void**)&p_logits, g_logits);
    cudaGetSymbolAddress((void**)&p_cnt, g_cnt);

    // 1) hid = tokens @ w1 (Eigen panel structure, FFMA2 inner)
    hid_gemm_kernel<<<dim3(4, 128, 1), 256>>>(tokens, w1, p_hid);
    // 2) scores = xla_sigmoid(relu(hid) . w2)
    score_gemv_kernel<<<16384 / 256, 256>>>(p_hid, w2, p_scores, 16384);
    // 3) per-batch descending stable sort
    sort_kernel<<<NB, 1024>>>(p_scores, p_sidx, p_sscore);
    // 4) summaries = sorted_tokens[:,:512] @ w_sum (batched, gathered A)
    sgemm128_kernel<0><<<dim3(2, 4, NB), 256>>>(
        tokens, w_sum, p_summ, 1024, 1024, 256, 256,
        (long)NT * ND, 0, (long)NP * NS, p_sidx, NT, 1.f);
    // 5) Q = tokens @ wq
    sgemm128_kernel<0><<<dim3(2, 128, 1), 256>>>(
        tokens, wq, p_Q, 1024, 1024, 256, 256, 0, 0, 0, nullptr, 0, 1.f);
    // 6) sequential pool update
    update_kernel<<<NB, 256>>>(pool, pri, counts, p_sscore, p_summ,
                               out_pool, out_pri, out_cnt, p_cnt);
    // 7) K = pool_out @ wk
    sgemm128_kernel<0><<<dim3(2, 32, 1), 256>>>(
        out_pool, wk, p_K, 256, 256, 256, 256, 0, 0, 0, nullptr, 0, 1.f);
    // 8) V = pool_out @ wv
    sgemm128_kernel<0><<<dim3(8, 32, 1), 256>>>(
        out_pool, wv, p_V, 256, 256, 1024, 1024, 0, 0, 0, nullptr, 0, 1.f);
    // 9) logits = Q @ K^T / 16 (batched)
    sgemm128_kernel<1><<<dim3(4, 16, NB), 256>>>(
        p_Q, p_K, p_logits, 256, 256, 256, 512,
        (long)NT * NS, (long)NP * NS, (long)NT * NP, nullptr, 0, 1.f / 16.f);
    // 10) masked softmax in place
    softmax_kernel<<<(16384 * 32) / 256, 256>>>(p_logits, p_cnt);
    // 11) retrieved = attn @ V (batched)
    sgemm128_kernel<0><<<dim3(8, 16, NB), 256>>>(
        p_logits, p_V, out_ret, 512, 512, 1024, 1024,
        (long)NT * NP, (long)NP * ND, (long)NT * ND, nullptr, 0, 1.f);
}

// round 8
// speedup vs baseline: 1.1913x; 1.1451x over previous
#include <cuda_runtime.h>
#include <cuda_bf16.h>
#include <math.h>
#include <stdint.h>

#define NB 8
#define NT 2048
#define ND 1024
#define NH 256
#define NP 512
#define NS 256

typedef unsigned long long u64;

// ---------------- scratch (static device globals; no allocation) ----------------
__device__ float g_hid[NB * NT * NH];      // 16 MB
__device__ float g_scores[NB * NT];
__device__ int   g_sidx[NB * NT];
__device__ float g_sscore[NB * NT];
__device__ float g_summ[NB * NP * NS];     // 4 MB
__device__ float g_Q[NB * NT * NS];        // 16 MB
__device__ float g_K[NB * NP * NS];        // 4 MB
__device__ float g_V[NB * NP * ND];        // 16 MB
__device__ float g_logits[NB * NT * NP];   // 32 MB
__device__ int   g_cnt[NB];

// ---------------- helpers ----------------
__device__ __forceinline__ uint32_t smem_u32(const void* p) {
    uint32_t a;
    asm("{ .reg .u64 t; cvta.to.shared.u64 t, %1; cvt.u32.u64 %0, t; }" : "=r"(a) : "l"(p));
    return a;
}
__device__ __forceinline__ void ldsm_x4(uint32_t* r, uint32_t addr) {
    asm volatile("ldmatrix.sync.aligned.m8n8.x4.shared.b16 {%0,%1,%2,%3}, [%4];"
                 : "=r"(r[0]), "=r"(r[1]), "=r"(r[2]), "=r"(r[3]) : "r"(addr));
}
__device__ __forceinline__ void ldsm_x2(uint32_t* r, uint32_t addr) {
    asm volatile("ldmatrix.sync.aligned.m8n8.x2.shared.b16 {%0,%1}, [%2];"
                 : "=r"(r[0]), "=r"(r[1]) : "r"(addr));
}
__device__ __forceinline__ void mma_bf16(float* c, const uint32_t* a, const uint32_t* b) {
    asm volatile(
        "mma.sync.aligned.m16n8k16.row.col.f32.bf16.bf16.f32 "
        "{%0,%1,%2,%3}, {%4,%5,%6,%7}, {%8,%9}, {%0,%1,%2,%3};"
        : "+f"(c[0]), "+f"(c[1]), "+f"(c[2]), "+f"(c[3])
        : "r"(a[0]), "r"(a[1]), "r"(a[2]), "r"(a[3]), "r"(b[0]), "r"(b[1]));
}
// split float -> (hi,lo) bf16 pair packed into u64 quads
__device__ __forceinline__ void split4(const float* x, u64& hp, u64& lp) {
    hp = 0; lp = 0;
#pragma unroll
    for (int j = 0; j < 4; j++) {
        __nv_bfloat16 h = __float2bfloat16(x[j]);
        float lo = x[j] - __bfloat162float(h);
        __nv_bfloat16 l = __float2bfloat16(lo);
        hp |= (u64)__bfloat16_as_ushort(h) << (16 * j);
        lp |= (u64)__bfloat16_as_ushort(l) << (16 * j);
    }
}

// ---------------- warp-MMA split-bf16 GEMM ----------------
// C[128x128/CTA] = alpha * A(MxK) * op(B). TRANSB==0: B[K,N]; TRANSB==1: B[N,K] (C=A*B^T).
// A optionally row-gathered. 3 passes (hi*hi + hi*lo + lo*hi), fp32 accum.
#define KC 32
#define SA 40   // smem row stride (elements), conflict-free for ldmatrix
template <int TRANSB, int GATHER>
__global__ void __launch_bounds__(256)
wmma_gemm_kernel(const float* __restrict__ A, const float* __restrict__ Bm,
                 float* __restrict__ C, int K,
                 int lda, int ldb, int ldc, long sA, long sB, long sC,
                 const int* __restrict__ arows, long sArows, float alpha) {
    __shared__ __nv_bfloat16 sAhi[128 * SA], sAlo[128 * SA];
    __shared__ __nv_bfloat16 sBhi[128 * SA], sBlo[128 * SA];   // B^T layout [n][k]

    const int bz = blockIdx.z;
    const float* Ab = A + (long)bz * sA;
    const float* Bb = Bm + (long)bz * sB;
    float* Cb = C + (long)bz * sC;
    const int* rows = GATHER ? (arows + (long)bz * sArows) : nullptr;
    const int m0 = blockIdx.y * 128;
    const int n0 = blockIdx.x * 128;

    const int tid = threadIdx.x;         // 256
    const int wid = tid >> 5, lane = tid & 31;
    const int wm = (wid & 3) * 32;       // 4 warps over M
    const int wn = (wid >> 2) * 64;      // 2 warps over N

    const uint32_t bAhi = smem_u32(sAhi), bAlo = smem_u32(sAlo);
    const uint32_t bBhi = smem_u32(sBhi), bBlo = smem_u32(sBlo);

    float c[2][8][4];
#pragma unroll
    for (int mt = 0; mt < 2; mt++)
#pragma unroll
        for (int nt = 0; nt < 8; nt++)
#pragma unroll
            for (int j = 0; j < 4; j++) c[mt][nt][j] = 0.f;

    // ldmatrix lane addressing (bytes)
    const int a_row = lane & 15, a_half = lane >> 4;          // x4: 16 rows x 2 col-halves
    const int bl_ = lane & 15;
    const int b_row = bl_ & 7, b_half = (bl_ >> 3) & 1;       // x2: 8 rows x 2 k-halves

    for (int k0 = 0; k0 < K; k0 += KC) {
        // ---- A chunk: 128 x 32 floats = 1024 float4 ----
#pragma unroll
        for (int i = 0; i < 4; i++) {
            int e = tid + i * 256;
            int r = e >> 3, cq = (e & 7) * 4;
            long gr = GATHER ? (long)rows[m0 + r] : (long)(m0 + r);
            float4 v = *(const float4*)(Ab + gr * (long)lda + k0 + cq);
            u64 hp, lp;
            split4(&v.x, hp, lp);
            *(u64*)&sAhi[r * SA + cq] = hp;
            *(u64*)&sAlo[r * SA + cq] = lp;
        }
        // ---- B chunk into B^T [n][k] ----
        if (TRANSB == 1) {
#pragma unroll
            for (int i = 0; i < 4; i++) {
                int e = tid + i * 256;
                int r = e >> 3, cq = (e & 7) * 4;
                float4 v = *(const float4*)(Bb + (long)(n0 + r) * ldb + k0 + cq);
                u64 hp, lp;
                split4(&v.x, hp, lp);
                *(u64*)&sBhi[r * SA + cq] = hp;
                *(u64*)&sBlo[r * SA + cq] = lp;
            }
        } else {
#pragma unroll
            for (int i = 0; i < 4; i++) {
                int e = tid + i * 256;
                int kk = e >> 5, nq = (e & 31) * 4;
                float4 v = *(const float4*)(Bb + (long)(k0 + kk) * ldb + n0 + nq);
                float x[4] = {v.x, v.y, v.z, v.w};
#pragma unroll
                for (int j = 0; j < 4; j++) {
                    __nv_bfloat16 h = __float2bfloat16(x[j]);
                    float lo = x[j] - __bfloat162float(h);
                    sBhi[(nq + j) * SA + kk] = h;
                    sBlo[(nq + j) * SA + kk] = __float2bfloat16(lo);
                }
            }
        }
        __syncthreads();

        // ---- compute ----
#pragma unroll
        for (int ks = 0; ks < 2; ks++) {
            const int kk = ks * 16;
            uint32_t ahi[2][4], alo[2][4];
#pragma unroll
            for (int mt = 0; mt < 2; mt++) {
                uint32_t off = (uint32_t)((wm + mt * 16 + a_row) * SA + kk + a_half * 8) * 2;
                ldsm_x4(ahi[mt], bAhi + off);
                ldsm_x4(alo[mt], bAlo + off);
            }
#pragma unroll
            for (int nt = 0; nt < 8; nt++) {
                uint32_t off = (uint32_t)((wn + nt * 8 + b_row) * SA + kk + b_half * 8) * 2;
                uint32_t bh[2], bl[2];
                ldsm_x2(bh, bBhi + off);
                ldsm_x2(bl, bBlo + off);
#pragma unroll
                for (int mt = 0; mt < 2; mt++) {
                    mma_bf16(c[mt][nt], ahi[mt], bh);
                    mma_bf16(c[mt][nt], alo[mt], bh);
                    mma_bf16(c[mt][nt], ahi[mt], bl);
                }
            }
        }
        __syncthreads();
    }

    // ---- epilogue: C fragment rows = lane/4 (+8), cols = (lane%4)*2 (+1) ----
#pragma unroll
    for (int mt = 0; mt < 2; mt++) {
#pragma unroll
        for (int nt = 0; nt < 8; nt++) {
            long r0 = m0 + wm + mt * 16 + (lane >> 2);
            int cc = n0 + wn + nt * 8 + (lane & 3) * 2;
            float2 v0 = make_float2(alpha * c[mt][nt][0], alpha * c[mt][nt][1]);
            float2 v1 = make_float2(alpha * c[mt][nt][2], alpha * c[mt][nt][3]);
            *(float2*)(Cb + r0 * (long)ldc + cc) = v0;
            *(float2*)(Cb + (r0 + 8) * (long)ldc + cc) = v1;
        }
    }
}

// ---------------- packed f32x2 helpers (compiled OK on sm_100 in R6) ----------------
__device__ __forceinline__ u64 pack2same(float x) {
    u64 r;
    asm("mov.b64 %0, {%1, %1};" : "=l"(r) : "r"(__float_as_uint(x)));
    return r;
}
__device__ __forceinline__ void ffma2(u64& d, u64 a, u64 b) {
    asm("fma.rn.f32x2 %0, %1, %2, %0;" : "+l"(d) : "l"(a), "l"(b));
}
__device__ __forceinline__ void fadd2(u64& d, u64 a) {
    asm("add.rn.f32x2 %0, %0, %1;" : "+l"(d) : "l"(a));
}
__device__ __forceinline__ void unpack2(u64 v, float& lo, float& hi) {
    unsigned a, b;
    asm("mov.b64 {%0, %1}, %2;" : "=r"(a), "=r"(b) : "l"(v));
    lo = __uint_as_float(a); hi = __uint_as_float(b);
}

// ---------------- hid GEMM with Eigen gebp K-panel structure (bit-exact fp32) ----------------
__global__ void __launch_bounds__(256, 2)
hid_gemm_kernel(const float* __restrict__ A, const float* __restrict__ Bm,
                float* __restrict__ C) {
    const int BM = 128, BN = 64, BK = 8;
    __shared__ float As[BK][BM + 4];
    __shared__ float Bs[BK][BN + 4];
    const int m0 = blockIdx.y * BM;
    const int n0 = blockIdx.x * BN;
    const int tid = threadIdx.x;
    const int tx = tid & 15;
    const int ty = tid >> 4;

    u64 tot2[8][2], pan2[8][2];
#pragma unroll
    for (int i = 0; i < 8; i++)
#pragma unroll
        for (int j = 0; j < 2; j++) { tot2[i][j] = 0ull; pan2[i][j] = 0ull; }

    for (int k0 = 0; k0 < 1024; k0 += BK) {
#pragma unroll
        for (int i = 0; i < 4; i++) {
            int e = tid + i * 256;
            int r = e >> 3, kk = e & 7;
            As[kk][r] = A[(long)(m0 + r) * 1024 + k0 + kk];
        }
#pragma unroll
        for (int i = 0; i < 2; i++) {
            int e = tid + i * 256;
            int kk = e >> 6, c = e & 63;
            Bs[kk][c] = Bm[(long)(k0 + kk) * 256 + n0 + c];
        }
        __syncthreads();
#pragma unroll
        for (int kk = 0; kk < BK; kk++) {
            u64 a2[8], b2[2];
#pragma unroll
            for (int i = 0; i < 8; i++) a2[i] = pack2same(As[kk][ty * 8 + i]);
#pragma unroll
            for (int j = 0; j < 2; j++)
                b2[j] = *(const u64*)&Bs[kk][tx * 4 + 2 * j];
#pragma unroll
            for (int i = 0; i < 8; i++)
#pragma unroll
                for (int j = 0; j < 2; j++) ffma2(pan2[i][j], a2[i], b2[j]);
        }
        __syncthreads();
        int kend = k0 + BK;
        if (kend == 248 || kend == 496 || kend == 744 || kend == 992 || kend == 1024) {
#pragma unroll
            for (int i = 0; i < 8; i++)
#pragma unroll
                for (int j = 0; j < 2; j++) {
                    fadd2(tot2[i][j], pan2[i][j]);
                    pan2[i][j] = 0ull;
                }
        }
    }
#pragma unroll
    for (int i = 0; i < 8; i++) {
        long r = m0 + ty * 8 + i;
        float o[4];
#pragma unroll
        for (int j = 0; j < 2; j++) unpack2(tot2[i][j], o[2 * j], o[2 * j + 1]);
        float* cp = C + r * 256 + n0 + tx * 4;
        *(float4*)cp = make_float4(o[0], o[1], o[2], o[3]);
    }
}

// ---------------- XLA-CPU f32 tanh + logistic (exact replica) ----------------
__device__ __forceinline__ float xla_tanh_f32(float x) {
    const float kClamp = 7.90531110763549805f;
    float xc = fminf(fmaxf(x, -kClamp), kClamp);
    float x2 = __fmul_rn(xc, xc);
    float p = -2.76076847742355e-16f;
    p = __fadd_rn(__fmul_rn(p, x2), 2.00018790482477e-13f);
    p = __fadd_rn(__fmul_rn(p, x2), -8.60467152213735e-11f);
    p = __fadd_rn(__fmul_rn(p, x2), 5.12229709037114e-08f);
    p = __fadd_rn(__fmul_rn(p, x2), 1.48572235717979e-05f);
    p = __fadd_rn(__fmul_rn(p, x2), 6.37261928875436e-04f);
    p = __fadd_rn(__fmul_rn(p, x2), 4.89352455891786e-03f);
    p = __fmul_rn(xc, p);
    float q = 1.19825839466702e-06f;
    q = __fadd_rn(__fmul_rn(q, x2), 1.18534705686654e-04f);
    q = __fadd_rn(__fmul_rn(q, x2), 2.26843463243900e-03f);
    q = __fadd_rn(__fmul_rn(q, x2), 4.89352518554385e-03f);
    float r = __fdiv_rn(p, q);
    return (fabsf(x) < 0.0004f) ? x : r;
}
__device__ __forceinline__ float xla_sigmoid_f32(float x) {
    return __fadd_rn(0.5f, __fmul_rn(0.5f, xla_tanh_f32(__fmul_rn(0.5f, x))));
}

// ---------------- scores: XLA-CPU tiled gemv replica ----------------
__global__ void score_gemv_kernel(const float* __restrict__ hid,
                                  const float* __restrict__ w2,
                                  float* __restrict__ scores, int nrows) {
    int r = blockIdx.x * blockDim.x + threadIdx.x;
    if (r >= nrows) return;
    const float* h = hid + (long)r * NH;
    float a0 = 0.f, a1 = 0.f, a2 = 0.f, a3 = 0.f;
#pragma unroll 4
    for (int k = 0; k < NH; k += 4) {
        float v0 = fmaxf(h[k + 0], 0.f);
        float v1 = fmaxf(h[k + 1], 0.f);
        float v2 = fmaxf(h[k + 2], 0.f);
        float v3 = fmaxf(h[k + 3], 0.f);
        a0 = __fadd_rn(__fmul_rn(v0, __ldg(&w2[k + 0])), a0);
        a1 = __fadd_rn(__fmul_rn(v1, __ldg(&w2[k + 1])), a1);
        a2 = __fadd_rn(__fmul_rn(v2, __ldg(&w2[k + 2])), a2);
        a3 = __fadd_rn(__fmul_rn(v3, __ldg(&w2[k + 3])), a3);
    }
    float s = __fadd_rn(__fadd_rn(a0, a2), __fadd_rn(a1, a3));
    scores[r] = xla_sigmoid_f32(s);
}

// ---------------- per-batch descending stable sort (bitonic over 2048) ----------------
__global__ void sort_kernel(const float* __restrict__ scores,
                            int* __restrict__ sidx, float* __restrict__ sscore) {
    __shared__ unsigned long long key[NT];
    const int b = blockIdx.x;
    const int tid = threadIdx.x;  // 1024
    for (int i = tid; i < NT; i += 1024) {
        unsigned int bits = __float_as_uint(scores[b * NT + i]);
        key[i] = ((unsigned long long)(0xFFFFFFFFu - bits) << 32) | (unsigned int)i;
    }
    __syncthreads();
    for (int k = 2; k <= NT; k <<= 1) {
        for (int j = k >> 1; j > 0; j >>= 1) {
            for (int i = tid; i < NT; i += 1024) {
                int p = i ^ j;
                if (p > i) {
                    bool up = ((i & k) == 0);
                    unsigned long long a = key[i], c = key[p];
                    if ((a > c) == up) { key[i] = c; key[p] = a; }
                }
            }
            __syncthreads();
        }
    }
    for (int i = tid; i < NT; i += 1024) {
        unsigned long long k = key[i];
        sidx[b * NT + i] = (int)(k & 0xFFFFFFFFull);
        sscore[b * NT + i] = __uint_as_float(0xFFFFFFFFu - (unsigned int)(k >> 32));
    }
}

// ---------------- sequential pool update (exact reference semantics) ----------------
__global__ void update_kernel(const float* __restrict__ pool_in,
                              const float* __restrict__ pri_in,
                              const int* __restrict__ counts_in,
                              const float* __restrict__ sscore,
                              const float* __restrict__ summ,
                              float* __restrict__ pool_out,
                              float* __restrict__ pri_out,
                              float* __restrict__ cnt_out_f,
                              int* __restrict__ cnt_out) {
    const int b = blockIdx.x;
    const int tid = threadIdx.x;  // 256
    const float4* src = (const float4*)(pool_in + (long)b * NP * NS);
    float4* dst = (float4*)(pool_out + (long)b * NP * NS);
    for (int i = tid; i < NP * NS / 4; i += 256) dst[i] = src[i];
    __syncthreads();
    if (tid >= 32) return;
    const int lane = tid;

    float pr[16];
#pragma unroll
    for (int j = 0; j < 16; j++) pr[j] = pri_in[b * NP + j * 32 + lane];
    int count = counts_in[b];
    const float* ss = sscore + (long)b * NT;

    for (int s = 0; s < NP; s++) {
        float imp = ss[s];
        if (!(imp > 0.5f)) break;
        const float4* srow = (const float4*)(summ + ((long)b * NP + s) * NS);
        if (count < NP) {
            int idx = count;
            float4* drow = (float4*)(pool_out + ((long)b * NP + idx) * NS);
            drow[lane] = srow[lane];
            drow[lane + 32] = srow[lane + 32];
            if ((idx & 31) == lane) pr[idx >> 5] = imp;
            count++;
        }
        if (count >= NP) {
            float bv = pr[0];
            int bi = lane;
#pragma unroll
            for (int j = 1; j < 16; j++) {
                float v = pr[j];
                if (v < bv) { bv = v; bi = j * 32 + lane; }
            }
#pragma unroll
            for (int o = 16; o > 0; o >>= 1) {
                float ov = __shfl_xor_sync(0xFFFFFFFFu, bv, o);
                int oi = __shfl_xor_sync(0xFFFFFFFFu, bi, o);
                if (ov < bv || (ov == bv && oi < bi)) { bv = ov; bi = oi; }
            }
            if (imp > bv) {
                float4* drow = (float4*)(pool_out + ((long)b * NP + bi) * NS);
                drow[lane] = srow[lane];
                drow[lane + 32] = srow[lane + 32];
                if ((bi & 31) == lane) pr[bi >> 5] = imp;
            }
        }
    }
#pragma unroll
    for (int j = 0; j < 16; j++) pri_out[b * NP + j * 32 + lane] = pr[j];
    if (lane == 0) { cnt_out_f[b] = (float)count; cnt_out[b] = count; }
}

// ---------------- masked softmax over P=512 (one warp per row, in place) ----------------
__global__ void softmax_kernel(float* __restrict__ logits, const int* __restrict__ cnt) {
    int row = (blockIdx.x * blockDim.x + threadIdx.x) >> 5;
    if (row >= NB * NT) return;
    const int lane = threadIdx.x & 31;
    const int b = row / NT;
    const int c = cnt[b];
    float* L = logits + (long)row * NP;
    float v[16];
    float mx = -INFINITY;
#pragma unroll
    for (int j = 0; j < 16; j++) {
        int p = j * 32 + lane;
        float x = (p < c) ? L[p] : -INFINITY;
        v[j] = x;
        mx = fmaxf(mx, x);
    }
#pragma unroll
    for (int o = 16; o > 0; o >>= 1) mx = fmaxf(mx, __shfl_xor_sync(0xFFFFFFFFu, mx, o));
    if (mx == -INFINITY) {
#pragma unroll
        for (int j = 0; j < 16; j++) v[j] = 0.f;
    } else {
        float sum = 0.f;
#pragma unroll
        for (int j = 0; j < 16; j++) {
            v[j] = (v[j] == -INFINITY) ? 0.f : expf(v[j] - mx);
            sum += v[j];
        }
#pragma unroll
        for (int o = 16; o > 0; o >>= 1) sum += __shfl_xor_sync(0xFFFFFFFFu, sum, o);
        float inv = 1.f / sum;
#pragma unroll
        for (int j = 0; j < 16; j++) v[j] *= inv;
    }
#pragma unroll
    for (int j = 0; j < 16; j++) L[j * 32 + lane] = v[j];
}

// ---------------- launch ----------------
extern "C" void kernel_launch(void* const* d_in, const int* in_sizes, int n_in,
                              void* d_out, int out_size) {
    const float* tokens = (const float*)d_in[0];
    const float* pool   = (const float*)d_in[1];
    const float* pri    = (const float*)d_in[2];
    const int*   counts = (const int*)d_in[3];
    const float* w1     = (const float*)d_in[4];
    const float* w2     = (const float*)d_in[5];
    const float* w_sum  = (const float*)d_in[6];
    const float* wq     = (const float*)d_in[7];
    const float* wk     = (const float*)d_in[8];
    const float* wv     = (const float*)d_in[9];

    float* out = (float*)d_out;
    float* out_ret  = out;                                   // [8,2048,1024]
    float* out_pool = out + (long)NB * NT * ND;              // [8,512,256]
    float* out_pri  = out_pool + (long)NB * NP * NS;         // [8,512]
    float* out_cnt  = out_pri + (long)NB * NP;               // [8]

    float *p_hid, *p_scores, *p_sscore, *p_summ, *p_Q, *p_K, *p_V, *p_logits;
    int *p_sidx, *p_cnt;
    cudaGetSymbolAddress((void**)&p_hid, g_hid);
    cudaGetSymbolAddress((void**)&p_scores, g_scores);
    cudaGetSymbolAddress((void**)&p_sidx, g_sidx);
    cudaGetSymbolAddress((void**)&p_sscore, g_sscore);
    cudaGetSymbolAddress((void**)&p_summ, g_summ);
    cudaGetSymbolAddress((void**)&p_Q, g_Q);
    cudaGetSymbolAddress((void**)&p_K, g_K);
    cudaGetSymbolAddress((void**)&p_V, g_V);
    cudaGetSymbolAddress((void**)&p_logits, g_logits);
    cudaGetSymbolAddress((void**)&p_cnt, g_cnt);

    // 1) hid = tokens @ w1 (bit-exact fp32, Eigen panel structure)
    hid_gemm_kernel<<<dim3(4, 128, 1), 256>>>(tokens, w1, p_hid);
    // 2) scores = xla_sigmoid(relu(hid) . w2)
    score_gemv_kernel<<<16384 / 256, 256>>>(p_hid, w2, p_scores, 16384);
    // 3) per-batch descending stable sort
    sort_kernel<<<NB, 1024>>>(p_scores, p_sidx, p_sscore);
    // 4) summaries = sorted_tokens[:,:512] @ w_sum (warp-mma, gathered A)
    wmma_gemm_kernel<0, 1><<<dim3(2, 4, NB), 256>>>(
        tokens, w_sum, p_summ, 1024, 1024, 256, 256,
        (long)NT * ND, 0, (long)NP * NS, p_sidx, NT, 1.f);
    // 5) Q = tokens @ wq (warp-mma)
    wmma_gemm_kernel<0, 0><<<dim3(2, 128, 1), 256>>>(
        tokens, wq, p_Q, 1024, 1024, 256, 256, 0, 0, 0, nullptr, 0, 1.f);
    // 6) sequential pool update
    update_kernel<<<NB, 256>>>(pool, pri, counts, p_sscore, p_summ,
                               out_pool, out_pri, out_cnt, p_cnt);
    // 7) K = pool_out @ wk (warp-mma)
    wmma_gemm_kernel<0, 0><<<dim3(2, 32, 1), 256>>>(
        out_pool, wk, p_K, 256, 256, 256, 256, 0, 0, 0, nullptr, 0, 1.f);
    // 8) V = pool_out @ wv (warp-mma)
    wmma_gemm_kernel<0, 0><<<dim3(8, 32, 1), 256>>>(
        out_pool, wv, p_V, 256, 256, 1024, 1024, 0, 0, 0, nullptr, 0, 1.f);
    // 9) logits = Q @ K^T / 16 (warp-mma, batched)
    wmma_gemm_kernel<1, 0><<<dim3(4, 16, NB), 256>>>(
        p_Q, p_K, p_logits, 256, 256, 256, 512,
        (long)NT * NS, (long)NP * NS, (long)NT * NP, nullptr, 0, 1.f / 16.f);
    // 10) masked softmax in place
    softmax_kernel<<<(16384 * 32) / 256, 256>>>(p_logits, p_cnt);
    // 11) retrieved = attn @ V (warp-mma, batched)
    wmma_gemm_kernel<0, 0><<<dim3(8, 16, NB), 256>>>(
        p_logits, p_V, out_ret, 512, 512, 1024, 1024,
        (long)NT * NP, (long)NP * ND, (long)NT * ND, nullptr, 0, 1.f);
}

// round 9
// speedup vs baseline: 1.6610x; 1.3943x over previous
#include <cuda_runtime.h>
#include <cuda_bf16.h>
#include <math.h>
#include <stdint.h>

#define NB 8
#define NT 2048
#define ND 1024
#define NH 256
#define NP 512
#define NS 256

typedef unsigned long long u64;
typedef __nv_bfloat16 bf16;

// ---------------- scratch (static device globals; no allocation) ----------------
__device__ float g_hid[NB * NT * NH];
__device__ float g_scores[NB * NT];
__device__ int   g_sidx[NB * NT];
__device__ float g_sscore[NB * NT];
__device__ float g_summ[NB * NP * NS];
__device__ float g_logits[NB * NT * NP];
__device__ int   g_cnt[NB];

__device__ __align__(16) bf16 g_tok_hi[NB * NT * ND];
__device__ __align__(16) bf16 g_tok_lo[NB * NT * ND];
__device__ __align__(16) bf16 g_wsT_hi[NS * ND], g_wsT_lo[NS * ND];
__device__ __align__(16) bf16 g_wqT_hi[NS * ND], g_wqT_lo[NS * ND];
__device__ __align__(16) bf16 g_wkT_hi[NS * NS], g_wkT_lo[NS * NS];
__device__ __align__(16) bf16 g_wvT_hi[ND * NS], g_wvT_lo[ND * NS];
__device__ __align__(16) bf16 g_pl_hi[NB * NP * NS], g_pl_lo[NB * NP * NS];
__device__ __align__(16) bf16 g_q_hi[NB * NT * NS], g_q_lo[NB * NT * NS];
__device__ __align__(16) bf16 g_k_hi[NB * NP * NS], g_k_lo[NB * NP * NS];
__device__ __align__(16) bf16 g_vT_hi[NB * ND * NP], g_vT_lo[NB * ND * NP];
__device__ __align__(16) bf16 g_a_hi[NB * NT * NP], g_a_lo[NB * NT * NP];

// ---------------- helpers ----------------
__device__ __forceinline__ uint32_t smem_u32(const void* p) {
    uint32_t a;
    asm("{ .reg .u64 t; cvta.to.shared.u64 t, %1; cvt.u32.u64 %0, t; }" : "=r"(a) : "l"(p));
    return a;
}
__device__ __forceinline__ void cp_async16(uint32_t dst, const void* src) {
    asm volatile("cp.async.cg.shared.global [%0], [%1], 16;" :: "r"(dst), "l"(src) : "memory");
}
__device__ __forceinline__ void cp_commit() {
    asm volatile("cp.async.commit_group;" ::: "memory");
}
__device__ __forceinline__ void cp_wait1() {
    asm volatile("cp.async.wait_group 1;" ::: "memory");
}
__device__ __forceinline__ void ldsm_x4(uint32_t* r, uint32_t addr) {
    asm volatile("ldmatrix.sync.aligned.m8n8.x4.shared.b16 {%0,%1,%2,%3}, [%4];"
                 : "=r"(r[0]), "=r"(r[1]), "=r"(r[2]), "=r"(r[3]) : "r"(addr));
}
__device__ __forceinline__ void ldsm_x2(uint32_t* r, uint32_t addr) {
    asm volatile("ldmatrix.sync.aligned.m8n8.x2.shared.b16 {%0,%1}, [%2];"
                 : "=r"(r[0]), "=r"(r[1]) : "r"(addr));
}
__device__ __forceinline__ void mma_bf16(float* c, const uint32_t* a, const uint32_t* b) {
    asm volatile(
        "mma.sync.aligned.m16n8k16.row.col.f32.bf16.bf16.f32 "
        "{%0,%1,%2,%3}, {%4,%5,%6,%7}, {%8,%9}, {%0,%1,%2,%3};"
        : "+f"(c[0]), "+f"(c[1]), "+f"(c[2]), "+f"(c[3])
        : "r"(a[0]), "r"(a[1]), "r"(a[2]), "r"(a[3]), "r"(b[0]), "r"(b[1]));
}
__device__ __forceinline__ void fsplit(float x, bf16& h, bf16& l) {
    h = __float2bfloat16(x);
    l = __float2bfloat16(x - __bfloat162float(h));
}

// ---------------- pipelined warp-MMA bf16-pair GEMM ----------------
// A[M,K] hi/lo (k-contig), B[N,K] hi/lo (k-contig). 3 passes, fp32 accum.
// EPI: 0 = fp32 C;  1 = bf16 hi/lo pair (row-major);  2 = bf16 pair transposed per 512-row batch.
#define STG_STRIDE 40960
template <int GATHER, int EPI>
__global__ void __launch_bounds__(256, 2)
gemm_bf16_kernel(const bf16* __restrict__ Ahi, const bf16* __restrict__ Alo,
                 const bf16* __restrict__ Bhi, const bf16* __restrict__ Blo,
                 float* __restrict__ C, bf16* __restrict__ Chi, bf16* __restrict__ Clo,
                 int K, int ldc, long sA, long sB, long sC,
                 const int* __restrict__ arows, long sArows, float alpha) {
    extern __shared__ char dsm[];
    __shared__ int srows[128];

    const int tid = threadIdx.x, wid = tid >> 5, lane = tid & 31;
    const int wm = (wid & 3) * 32, wn = (wid >> 2) * 64;
    const int bz = blockIdx.z;
    const int m0 = blockIdx.y * 128, n0 = blockIdx.x * 128;
    const bf16* Ah = Ahi + (long)bz * sA;
    const bf16* Al = Alo + (long)bz * sA;
    const bf16* Bh = Bhi + (long)bz * sB;
    const bf16* Bl = Blo + (long)bz * sB;

    if (GATHER) {
        if (tid < 128) srows[tid] = arows[(long)bz * sArows + m0 + tid];
        __syncthreads();
    }
    const uint32_t sbase = smem_u32(dsm);

    float c[2][8][4];
#pragma unroll
    for (int mt = 0; mt < 2; mt++)
#pragma unroll
        for (int nt = 0; nt < 8; nt++)
#pragma unroll
            for (int j = 0; j < 4; j++) c[mt][nt][j] = 0.f;

    const int a_row = lane & 15, a_half = lane >> 4;
    const int b_row = lane & 7, b_half = (lane >> 3) & 1;

    auto issue = [&](int ch) {
        uint32_t st = sbase + (ch & 1) * STG_STRIDE;
        int k0 = ch * 32;
#pragma unroll
        for (int i = 0; i < 2; i++) {
            int e = tid + i * 256;
            int r = e >> 2, q = e & 3;
            long gr = GATHER ? (long)srows[r] : (long)(m0 + r);
            long go = gr * (long)K + k0 + q * 8;
            uint32_t so = (uint32_t)(r * 80 + q * 16);
            cp_async16(st + so, Ah + go);
            cp_async16(st + 10240 + so, Al + go);
        }
#pragma unroll
        for (int i = 0; i < 2; i++) {
            int e = tid + i * 256;
            int r = e >> 2, q = e & 3;
            long go = (long)(n0 + r) * K + k0 + q * 8;
            uint32_t so = (uint32_t)(r * 80 + q * 16);
            cp_async16(st + 20480 + so, Bh + go);
            cp_async16(st + 30720 + so, Bl + go);
        }
    };
    auto compute = [&](int s) {
        uint32_t st = sbase + s * STG_STRIDE;
#pragma unroll
        for (int ks = 0; ks < 2; ks++) {
            int kk = ks * 16;
            uint32_t ahi[2][4], alo[2][4];
#pragma unroll
            for (int mt = 0; mt < 2; mt++) {
                uint32_t off = (uint32_t)((wm + mt * 16 + a_row) * 40 + kk + a_half * 8) * 2;
                ldsm_x4(ahi[mt], st + off);
                ldsm_x4(alo[mt], st + 10240 + off);
            }
#pragma unroll
            for (int nt = 0; nt < 8; nt++) {
                uint32_t off = (uint32_t)((wn + nt * 8 + b_row) * 40 + kk + b_half * 8) * 2;
                uint32_t bh[2], bl[2];
                ldsm_x2(bh, st + 20480 + off);
                ldsm_x2(bl, st + 30720 + off);
#pragma unroll
                for (int mt = 0; mt < 2; mt++) {
                    mma_bf16(c[mt][nt], ahi[mt], bh);
                    mma_bf16(c[mt][nt], alo[mt], bh);
                    mma_bf16(c[mt][nt], ahi[mt], bl);
                }
            }
        }
    };

    const int nch = K >> 5;
    issue(0); cp_commit();
    if (nch > 1) issue(1);
    cp_commit();
    for (int ch = 0; ch < nch; ch++) {
        cp_wait1();
        __syncthreads();
        compute(ch & 1);
        __syncthreads();
        if (ch + 2 < nch) issue(ch + 2);
        cp_commit();
    }

    // ---- epilogue ----
#pragma unroll
    for (int mt = 0; mt < 2; mt++) {
#pragma unroll
        for (int nt = 0; nt < 8; nt++) {
            long r0 = m0 + wm + mt * 16 + (lane >> 2);
            int cc = n0 + wn + nt * 8 + (lane & 3) * 2;
            float x0 = alpha * c[mt][nt][0], x1 = alpha * c[mt][nt][1];
            float x2 = alpha * c[mt][nt][2], x3 = alpha * c[mt][nt][3];
            if (EPI == 0) {
                float* Cb = C + (long)bz * sC;
                *(float2*)(Cb + r0 * (long)ldc + cc) = make_float2(x0, x1);
                *(float2*)(Cb + (r0 + 8) * (long)ldc + cc) = make_float2(x2, x3);
            } else if (EPI == 1) {
                bf16 h0, l0, h1, l1, h2, l2, h3, l3;
                fsplit(x0, h0, l0); fsplit(x1, h1, l1);
                fsplit(x2, h2, l2); fsplit(x3, h3, l3);
                uint32_t hp0 = (uint32_t)__bfloat16_as_ushort(h0) | ((uint32_t)__bfloat16_as_ushort(h1) << 16);
                uint32_t lp0 = (uint32_t)__bfloat16_as_ushort(l0) | ((uint32_t)__bfloat16_as_ushort(l1) << 16);
                uint32_t hp1 = (uint32_t)__bfloat16_as_ushort(h2) | ((uint32_t)__bfloat16_as_ushort(h3) << 16);
                uint32_t lp1 = (uint32_t)__bfloat16_as_ushort(l2) | ((uint32_t)__bfloat16_as_ushort(l3) << 16);
                *(uint32_t*)(Chi + r0 * (long)ldc + cc) = hp0;
                *(uint32_t*)(Clo + r0 * (long)ldc + cc) = lp0;
                *(uint32_t*)(Chi + (r0 + 8) * (long)ldc + cc) = hp1;
                *(uint32_t*)(Clo + (r0 + 8) * (long)ldc + cc) = lp1;
            } else {
                // transposed per 512-row batch: out[b][col][row], row-len NP
                long b = r0 >> 9;
                long p = r0 & 511;
                bf16* oh = Chi + b * (long)(ND * NP);
                bf16* ol = Clo + b * (long)(ND * NP);
                bf16 h, l;
                fsplit(x0, h, l); oh[(long)cc * NP + p] = h;       ol[(long)cc * NP + p] = l;
                fsplit(x1, h, l); oh[(long)(cc + 1) * NP + p] = h; ol[(long)(cc + 1) * NP + p] = l;
                fsplit(x2, h, l); oh[(long)cc * NP + p + 8] = h;       ol[(long)cc * NP + p + 8] = l;
                fsplit(x3, h, l); oh[(long)(cc + 1) * NP + p + 8] = h; ol[(long)(cc + 1) * NP + p + 8] = l;
            }
        }
    }
}

// ---------------- split / transpose-split ----------------
__global__ void split_kernel(const float4* __restrict__ src, bf16* __restrict__ hi,
                             bf16* __restrict__ lo, int n4) {
    int i = blockIdx.x * blockDim.x + threadIdx.x;
    if (i >= n4) return;
    float4 v = src[i];
    float x[4] = {v.x, v.y, v.z, v.w};
    u64 hp = 0, lp = 0;
#pragma unroll
    for (int j = 0; j < 4; j++) {
        bf16 h, l;
        fsplit(x[j], h, l);
        hp |= (u64)__bfloat16_as_ushort(h) << (16 * j);
        lp |= (u64)__bfloat16_as_ushort(l) << (16 * j);
    }
    *(u64*)(hi + 4 * (long)i) = hp;
    *(u64*)(lo + 4 * (long)i) = lp;
}
// w[KK][NN] fp32 -> out[NN][KK] bf16 pairs
__global__ void tsplit_kernel(const float* __restrict__ w, bf16* __restrict__ thi,
                              bf16* __restrict__ tlo, int KK, int NN) {
    int o = blockIdx.x * blockDim.x + threadIdx.x;
    if (o >= KK * NN) return;
    int n = o / KK, k = o % KK;
    bf16 h, l;
    fsplit(w[(long)k * NN + n], h, l);
    thi[o] = h; tlo[o] = l;
}

// ---------------- packed f32x2 helpers ----------------
__device__ __forceinline__ u64 pack2same(float x) {
    u64 r;
    asm("mov.b64 %0, {%1, %1};" : "=l"(r) : "r"(__float_as_uint(x)));
    return r;
}
__device__ __forceinline__ void ffma2(u64& d, u64 a, u64 b) {
    asm("fma.rn.f32x2 %0, %1, %2, %0;" : "+l"(d) : "l"(a), "l"(b));
}
__device__ __forceinline__ void fadd2(u64& d, u64 a) {
    asm("add.rn.f32x2 %0, %0, %1;" : "+l"(d) : "l"(a));
}
__device__ __forceinline__ void unpack2(u64 v, float& lo, float& hi) {
    unsigned a, b;
    asm("mov.b64 {%0, %1}, %2;" : "=r"(a), "=r"(b) : "l"(v));
    lo = __uint_as_float(a); hi = __uint_as_float(b);
}

// ---------------- hid GEMM, Eigen gebp kc=248 panels (bit-exact fp32) ----------------
__global__ void __launch_bounds__(256, 2)
hid_gemm_kernel(const float* __restrict__ A, const float* __restrict__ Bm,
                float* __restrict__ C) {
    const int BM = 128, BN = 64, BK = 8;
    __shared__ float As[BK][BM + 4];
    __shared__ float Bs[BK][BN + 4];
    const int m0 = blockIdx.y * BM;
    const int n0 = blockIdx.x * BN;
    const int tid = threadIdx.x;
    const int tx = tid & 15;
    const int ty = tid >> 4;

    u64 tot2[8][2], pan2[8][2];
#pragma unroll
    for (int i = 0; i < 8; i++)
#pragma unroll
        for (int j = 0; j < 2; j++) { tot2[i][j] = 0ull; pan2[i][j] = 0ull; }

    for (int k0 = 0; k0 < 1024; k0 += BK) {
#pragma unroll
        for (int i = 0; i < 4; i++) {
            int e = tid + i * 256;
            int r = e >> 3, kk = e & 7;
            As[kk][r] = A[(long)(m0 + r) * 1024 + k0 + kk];
        }
#pragma unroll
        for (int i = 0; i < 2; i++) {
            int e = tid + i * 256;
            int kk = e >> 6, c = e & 63;
            Bs[kk][c] = Bm[(long)(k0 + kk) * 256 + n0 + c];
        }
        __syncthreads();
#pragma unroll
        for (int kk = 0; kk < BK; kk++) {
            u64 a2[8], b2[2];
#pragma unroll
            for (int i = 0; i < 8; i++) a2[i] = pack2same(As[kk][ty * 8 + i]);
#pragma unroll
            for (int j = 0; j < 2; j++)
                b2[j] = *(const u64*)&Bs[kk][tx * 4 + 2 * j];
#pragma unroll
            for (int i = 0; i < 8; i++)
#pragma unroll
                for (int j = 0; j < 2; j++) ffma2(pan2[i][j], a2[i], b2[j]);
        }
        __syncthreads();
        int kend = k0 + BK;
        if (kend == 248 || kend == 496 || kend == 744 || kend == 992 || kend == 1024) {
#pragma unroll
            for (int i = 0; i < 8; i++)
#pragma unroll
                for (int j = 0; j < 2; j++) {
                    fadd2(tot2[i][j], pan2[i][j]);
                    pan2[i][j] = 0ull;
                }
        }
    }
#pragma unroll
    for (int i = 0; i < 8; i++) {
        long r = m0 + ty * 8 + i;
        float o[4];
#pragma unroll
        for (int j = 0; j < 2; j++) unpack2(tot2[i][j], o[2 * j], o[2 * j + 1]);
        float* cp = C + r * 256 + n0 + tx * 4;
        *(float4*)cp = make_float4(o[0], o[1], o[2], o[3]);
    }
}

// ---------------- XLA-CPU tanh / logistic (bit-exact) ----------------
__device__ __forceinline__ float xla_tanh_f32(float x) {
    const float kClamp = 7.90531110763549805f;
    float xc = fminf(fmaxf(x, -kClamp), kClamp);
    float x2 = __fmul_rn(xc, xc);
    float p = -2.76076847742355e-16f;
    p = __fadd_rn(__fmul_rn(p, x2), 2.00018790482477e-13f);
    p = __fadd_rn(__fmul_rn(p, x2), -8.60467152213735e-11f);
    p = __fadd_rn(__fmul_rn(p, x2), 5.12229709037114e-08f);
    p = __fadd_rn(__fmul_rn(p, x2), 1.48572235717979e-05f);
    p = __fadd_rn(__fmul_rn(p, x2), 6.37261928875436e-04f);
    p = __fadd_rn(__fmul_rn(p, x2), 4.89352455891786e-03f);
    p = __fmul_rn(xc, p);
    float q = 1.19825839466702e-06f;
    q = __fadd_rn(__fmul_rn(q, x2), 1.18534705686654e-04f);
    q = __fadd_rn(__fmul_rn(q, x2), 2.26843463243900e-03f);
    q = __fadd_rn(__fmul_rn(q, x2), 4.89352518554385e-03f);
    float r = __fdiv_rn(p, q);
    return (fabsf(x) < 0.0004f) ? x : r;
}
__device__ __forceinline__ float xla_sigmoid_f32(float x) {
    return __fadd_rn(0.5f, __fmul_rn(0.5f, xla_tanh_f32(__fmul_rn(0.5f, x))));
}

__global__ void score_gemv_kernel(const float* __restrict__ hid,
                                  const float* __restrict__ w2,
                                  float* __restrict__ scores, int nrows) {
    int r = blockIdx.x * blockDim.x + threadIdx.x;
    if (r >= nrows) return;
    const float* h = hid + (long)r * NH;
    float a0 = 0.f, a1 = 0.f, a2 = 0.f, a3 = 0.f;
#pragma unroll 4
    for (int k = 0; k < NH; k += 4) {
        float v0 = fmaxf(h[k + 0], 0.f);
        float v1 = fmaxf(h[k + 1], 0.f);
        float v2 = fmaxf(h[k + 2], 0.f);
        float v3 = fmaxf(h[k + 3], 0.f);
        a0 = __fadd_rn(__fmul_rn(v0, __ldg(&w2[k + 0])), a0);
        a1 = __fadd_rn(__fmul_rn(v1, __ldg(&w2[k + 1])), a1);
        a2 = __fadd_rn(__fmul_rn(v2, __ldg(&w2[k + 2])), a2);
        a3 = __fadd_rn(__fmul_rn(v3, __ldg(&w2[k + 3])), a3);
    }
    float s = __fadd_rn(__fadd_rn(a0, a2), __fadd_rn(a1, a3));
    scores[r] = xla_sigmoid_f32(s);
}

// ---------------- bitonic sort ----------------
__global__ void sort_kernel(const float* __restrict__ scores,
                            int* __restrict__ sidx, float* __restrict__ sscore) {
    __shared__ unsigned long long key[NT];
    const int b = blockIdx.x;
    const int tid = threadIdx.x;
    for (int i = tid; i < NT; i += 1024) {
        unsigned int bits = __float_as_uint(scores[b * NT + i]);
        key[i] = ((unsigned long long)(0xFFFFFFFFu - bits) << 32) | (unsigned int)i;
    }
    __syncthreads();
    for (int k = 2; k <= NT; k <<= 1) {
        for (int j = k >> 1; j > 0; j >>= 1) {
            for (int i = tid; i < NT; i += 1024) {
                int p = i ^ j;
                if (p > i) {
                    bool up = ((i & k) == 0);
                    unsigned long long a = key[i], c = key[p];
                    if ((a > c) == up) { key[i] = c; key[p] = a; }
                }
            }
            __syncthreads();
        }
    }
    for (int i = tid; i < NT; i += 1024) {
        unsigned long long k = key[i];
        sidx[b * NT + i] = (int)(k & 0xFFFFFFFFull);
        sscore[b * NT + i] = __uint_as_float(0xFFFFFFFFu - (unsigned int)(k >> 32));
    }
}

// ---------------- sequential pool update ----------------
__global__ void update_kernel(const float* __restrict__ pool_in,
                              const float* __restrict__ pri_in,
                              const int* __restrict__ counts_in,
                              const float* __restrict__ sscore,
                              const float* __restrict__ summ,
                              float* __restrict__ pool_out,
                              float* __restrict__ pri_out,
                              float* __restrict__ cnt_out_f,
                              int* __restrict__ cnt_out) {
    const int b = blockIdx.x;
    const int tid = threadIdx.x;
    const float4* src = (const float4*)(pool_in + (long)b * NP * NS);
    float4* dst = (float4*)(pool_out + (long)b * NP * NS);
    for (int i = tid; i < NP * NS / 4; i += 256) dst[i] = src[i];
    __syncthreads();
    if (tid >= 32) return;
    const int lane = tid;

    float pr[16];
#pragma unroll
    for (int j = 0; j < 16; j++) pr[j] = pri_in[b * NP + j * 32 + lane];
    int count = counts_in[b];
    const float* ss = sscore + (long)b * NT;

    for (int s = 0; s < NP; s++) {
        float imp = ss[s];
        if (!(imp > 0.5f)) break;
        const float4* srow = (const float4*)(summ + ((long)b * NP + s) * NS);
        if (count < NP) {
            int idx = count;
            float4* drow = (float4*)(pool_out + ((long)b * NP + idx) * NS);
            drow[lane] = srow[lane];
            drow[lane + 32] = srow[lane + 32];
            if ((idx & 31) == lane) pr[idx >> 5] = imp;
            count++;
        }
        if (count >= NP) {
            float bv = pr[0];
            int bi = lane;
#pragma unroll
            for (int j = 1; j < 16; j++) {
                float v = pr[j];
                if (v < bv) { bv = v; bi = j * 32 + lane; }
            }
#pragma unroll
            for (int o = 16; o > 0; o >>= 1) {
                float ov = __shfl_xor_sync(0xFFFFFFFFu, bv, o);
                int oi = __shfl_xor_sync(0xFFFFFFFFu, bi, o);
                if (ov < bv || (ov == bv && oi < bi)) { bv = ov; bi = oi; }
            }
            if (imp > bv) {
                float4* drow = (float4*)(pool_out + ((long)b * NP + bi) * NS);
                drow[lane] = srow[lane];
                drow[lane + 32] = srow[lane + 32];
                if ((bi & 31) == lane) pr[bi >> 5] = imp;
            }
        }
    }
#pragma unroll
    for (int j = 0; j < 16; j++) pri_out[b * NP + j * 32 + lane] = pr[j];
    if (lane == 0) { cnt_out_f[b] = (float)count; cnt_out[b] = count; }
}

// ---------------- masked softmax -> bf16 hi/lo attn weights ----------------
__global__ void softmax_bf16_kernel(const float* __restrict__ logits,
                                    const int* __restrict__ cnt,
                                    bf16* __restrict__ ahi, bf16* __restrict__ alo) {
    int row = (blockIdx.x * blockDim.x + threadIdx.x) >> 5;
    if (row >= NB * NT) return;
    const int lane = threadIdx.x & 31;
    const int b = row / NT;
    const int c = cnt[b];
    const float* L = logits + (long)row * NP;
    float v[16];
    float mx = -INFINITY;
#pragma unroll
    for (int j = 0; j < 16; j++) {
        int p = j * 32 + lane;
        float x = (p < c) ? L[p] : -INFINITY;
        v[j] = x;
        mx = fmaxf(mx, x);
    }
#pragma unroll
    for (int o = 16; o > 0; o >>= 1) mx = fmaxf(mx, __shfl_xor_sync(0xFFFFFFFFu, mx, o));
    if (mx == -INFINITY) {
#pragma unroll
        for (int j = 0; j < 16; j++) v[j] = 0.f;
    } else {
        float sum = 0.f;
#pragma unroll
        for (int j = 0; j < 16; j++) {
            v[j] = (v[j] == -INFINITY) ? 0.f : expf(v[j] - mx);
            sum += v[j];
        }
#pragma unroll
        for (int o = 16; o > 0; o >>= 1) sum += __shfl_xor_sync(0xFFFFFFFFu, sum, o);
        float inv = 1.f / sum;
#pragma unroll
        for (int j = 0; j < 16; j++) v[j] *= inv;
    }
#pragma unroll
    for (int j = 0; j < 16; j++) {
        int p = j * 32 + lane;
        bf16 h, l;
        fsplit(v[j], h, l);
        ahi[(long)row * NP + p] = h;
        alo[(long)row * NP + p] = l;
    }
}

// ---------------- launch ----------------
extern "C" void kernel_launch(void* const* d_in, const int* in_sizes, int n_in,
                              void* d_out, int out_size) {
    const float* tokens = (const float*)d_in[0];
    const float* pool   = (const float*)d_in[1];
    const float* pri    = (const float*)d_in[2];
    const int*   counts = (const int*)d_in[3];
    const float* w1     = (const float*)d_in[4];
    const float* w2     = (const float*)d_in[5];
    const float* w_sum  = (const float*)d_in[6];
    const float* wq     = (const float*)d_in[7];
    const float* wk     = (const float*)d_in[8];
    const float* wv     = (const float*)d_in[9];

    float* out = (float*)d_out;
    float* out_ret  = out;
    float* out_pool = out + (long)NB * NT * ND;
    float* out_pri  = out_pool + (long)NB * NP * NS;
    float* out_cnt  = out_pri + (long)NB * NP;

    float *p_hid, *p_scores, *p_sscore, *p_summ, *p_logits;
    int *p_sidx, *p_cnt;
    bf16 *tok_hi, *tok_lo, *wsT_hi, *wsT_lo, *wqT_hi, *wqT_lo, *wkT_hi, *wkT_lo, *wvT_hi, *wvT_lo;
    bf16 *pl_hi, *pl_lo, *q_hi, *q_lo, *k_hi, *k_lo, *vT_hi, *vT_lo, *a_hi, *a_lo;
    cudaGetSymbolAddress((void**)&p_hid, g_hid);
    cudaGetSymbolAddress((void**)&p_scores, g_scores);
    cudaGetSymbolAddress((void**)&p_sidx, g_sidx);
    cudaGetSymbolAddress((void**)&p_sscore, g_sscore);
    cudaGetSymbolAddress((void**)&p_summ, g_summ);
    cudaGetSymbolAddress((void**)&p_logits, g_logits);
    cudaGetSymbolAddress((void**)&p_cnt, g_cnt);
    cudaGetSymbolAddress((void**)&tok_hi, g_tok_hi);
    cudaGetSymbolAddress((void**)&tok_lo, g_tok_lo);
    cudaGetSymbolAddress((void**)&wsT_hi, g_wsT_hi);
    cudaGetSymbolAddress((void**)&wsT_lo, g_wsT_lo);
    cudaGetSymbolAddress((void**)&wqT_hi, g_wqT_hi);
    cudaGetSymbolAddress((void**)&wqT_lo, g_wqT_lo);
    cudaGetSymbolAddress((void**)&wkT_hi, g_wkT_hi);
    cudaGetSymbolAddress((void**)&wkT_lo, g_wkT_lo);
    cudaGetSymbolAddress((void**)&wvT_hi, g_wvT_hi);
    cudaGetSymbolAddress((void**)&wvT_lo, g_wvT_lo);
    cudaGetSymbolAddress((void**)&pl_hi, g_pl_hi);
    cudaGetSymbolAddress((void**)&pl_lo, g_pl_lo);
    cudaGetSymbolAddress((void**)&q_hi, g_q_hi);
    cudaGetSymbolAddress((void**)&q_lo, g_q_lo);
    cudaGetSymbolAddress((void**)&k_hi, g_k_hi);
    cudaGetSymbolAddress((void**)&k_lo, g_k_lo);
    cudaGetSymbolAddress((void**)&vT_hi, g_vT_hi);
    cudaGetSymbolAddress((void**)&vT_lo, g_vT_lo);
    cudaGetSymbolAddress((void**)&a_hi, g_a_hi);
    cudaGetSymbolAddress((void**)&a_lo, g_a_lo);

    const int GSM = 2 * STG_STRIDE;   // 81920 B dynamic smem
    cudaFuncSetAttribute(gemm_bf16_kernel<0, 0>, cudaFuncAttributeMaxDynamicSharedMemorySize, GSM);
    cudaFuncSetAttribute(gemm_bf16_kernel<1, 0>, cudaFuncAttributeMaxDynamicSharedMemorySize, GSM);
    cudaFuncSetAttribute(gemm_bf16_kernel<0, 1>, cudaFuncAttributeMaxDynamicSharedMemorySize, GSM);
    cudaFuncSetAttribute(gemm_bf16_kernel<0, 2>, cudaFuncAttributeMaxDynamicSharedMemorySize, GSM);

    // pre-splits
    split_kernel<<<(NB * NT * ND / 4 + 255) / 256, 256>>>((const float4*)tokens, tok_hi, tok_lo, NB * NT * ND / 4);
    tsplit_kernel<<<(ND * NS + 255) / 256, 256>>>(w_sum, wsT_hi, wsT_lo, ND, NS);
    tsplit_kernel<<<(ND * NS + 255) / 256, 256>>>(wq, wqT_hi, wqT_lo, ND, NS);
    tsplit_kernel<<<(NS * NS + 255) / 256, 256>>>(wk, wkT_hi, wkT_lo, NS, NS);
    tsplit_kernel<<<(NS * ND + 255) / 256, 256>>>(wv, wvT_hi, wvT_lo, NS, ND);

    // score path (bit-exact)
    hid_gemm_kernel<<<dim3(4, 128, 1), 256>>>(tokens, w1, p_hid);
    score_gemv_kernel<<<16384 / 256, 256>>>(p_hid, w2, p_scores, 16384);
    sort_kernel<<<NB, 1024>>>(p_scores, p_sidx, p_sscore);

    // summaries (gathered A, fp32 out)
    gemm_bf16_kernel<1, 0><<<dim3(2, 4, NB), 256, GSM>>>(
        tok_hi, tok_lo, wsT_hi, wsT_lo, p_summ, nullptr, nullptr,
        1024, 256, (long)NT * ND, 0, (long)NP * NS, p_sidx, NT, 1.f);
    // Q (bf16-pair out)
    gemm_bf16_kernel<0, 1><<<dim3(2, 128, 1), 256, GSM>>>(
        tok_hi, tok_lo, wqT_hi, wqT_lo, nullptr, q_hi, q_lo,
        1024, 256, 0, 0, 0, nullptr, 0, 1.f);
    // pool update
    update_kernel<<<NB, 256>>>(pool, pri, counts, p_sscore, p_summ,
                               out_pool, out_pri, out_cnt, p_cnt);
    // split pool_out
    split_kernel<<<(NB * NP * NS / 4 + 255) / 256, 256>>>((const float4*)out_pool, pl_hi, pl_lo, NB * NP * NS / 4);
    // K (bf16-pair out)
    gemm_bf16_kernel<0, 1><<<dim3(2, 32, 1), 256, GSM>>>(
        pl_hi, pl_lo, wkT_hi, wkT_lo, nullptr, k_hi, k_lo,
        256, 256, 0, 0, 0, nullptr, 0, 1.f);
    // V (bf16-pair transposed out)
    gemm_bf16_kernel<0, 2><<<dim3(8, 32, 1), 256, GSM>>>(
        pl_hi, pl_lo, wvT_hi, wvT_lo, nullptr, vT_hi, vT_lo,
        256, 0, 0, 0, 0, nullptr, 0, 1.f);
    // logits (fp32 out, /16)
    gemm_bf16_kernel<0, 0><<<dim3(4, 16, NB), 256, GSM>>>(
        q_hi, q_lo, k_hi, k_lo, p_logits, nullptr, nullptr,
        256, 512, (long)NT * NS, (long)NP * NS, (long)NT * NP, nullptr, 0, 1.f / 16.f);
    // softmax -> bf16 pairs
    softmax_bf16_kernel<<<(16384 * 32) / 256, 256>>>(p_logits, p_cnt, a_hi, a_lo);
    // retrieved = attn @ V
    gemm_bf16_kernel<0, 0><<<dim3(8, 16, NB), 256, GSM>>>(
        a_hi, a_lo, vT_hi, vT_lo, out_ret, nullptr, nullptr,
        512, 1024, (long)NT * NP, (long)ND * NP, (long)NT * ND, nullptr, 0, 1.f);
}